// round 1
// baseline (speedup 1.0000x reference)
#include <cuda_runtime.h>
#include <math.h>

#define Bn 8
#define Cn 128
#define Nn 20000
#define TN 64
#define SPL 18
#define SPLEN 1152          // 18*64, SPL*SPLEN = 20736 >= 20000
#define INVT 0.08838834764831845f  // 1/sqrt(128)

// ---- device scratch (static, allocation-free) ----
__device__ __align__(16) float d_Wq[Cn * Cn];   // [c][o], BN scale * 1/temp folded
__device__ __align__(16) float d_Wk[Cn * Cn];   // [c][o], BN scale folded
__device__ __align__(16) float d_Wv[Cn * Cn];   // [c][o], BN scale folded
__device__ float d_sq[Cn], d_sk[Cn], d_sv[Cn];
__device__ float d_wgb[Cn * 5];                 // per o: wg1_0, wg1_1, wg2_0, wg2_1, bg1+bg2
__device__ __align__(16) float d_attn_part[Bn * SPL * Cn * Cn]; // 9.4 MB partials
__device__ __align__(16) float d_attnT[Bn * Cn * Cn];           // softmaxed attn, [b][d][c]

// ---------------------------------------------------------------------------
// prep: fold BN affine (and 1/temp for q) into weights; build graph-bias table
// ---------------------------------------------------------------------------
__global__ void prep_kernel(
    const float* __restrict__ Wq, const float* __restrict__ gq, const float* __restrict__ bq,
    const float* __restrict__ mq, const float* __restrict__ vq,
    const float* __restrict__ Wk, const float* __restrict__ gk, const float* __restrict__ bk,
    const float* __restrict__ mk, const float* __restrict__ vk,
    const float* __restrict__ Wv, const float* __restrict__ gv, const float* __restrict__ bv,
    const float* __restrict__ mv, const float* __restrict__ vv,
    const float* __restrict__ Wg1, const float* __restrict__ bg1,
    const float* __restrict__ Wg2, const float* __restrict__ bg2)
{
    int o = blockIdx.x;
    int c = threadIdx.x;
    float scq = gq[o] / sqrtf(vq[o] + 1e-5f);
    float sck = gk[o] / sqrtf(vk[o] + 1e-5f);
    float scv = gv[o] / sqrtf(vv[o] + 1e-5f);
    d_Wq[c * Cn + o] = Wq[o * Cn + c] * scq * INVT;
    d_Wk[c * Cn + o] = Wk[o * Cn + c] * sck;
    d_Wv[c * Cn + o] = Wv[o * Cn + c] * scv;
    if (c == 0) {
        d_sq[o] = (bq[o] - mq[o] * scq) * INVT;
        d_sk[o] = bk[o] - mk[o] * sck;
        d_sv[o] = bv[o] - mv[o] * scv;
        d_wgb[o * 5 + 0] = Wg1[o * 2 + 0];
        d_wgb[o * 5 + 1] = Wg1[o * 2 + 1];
        d_wgb[o * 5 + 2] = Wg2[o * 2 + 0];
        d_wgb[o * 5 + 3] = Wg2[o * 2 + 1];
        d_wgb[o * 5 + 4] = bg1[o] + bg2[o];
    }
}

// ---------------------------------------------------------------------------
// pass1: per (split, b) block — compute q, k+gc chunks on the fly and
// accumulate attn partials (128x128) in registers. No q/k ever hit HBM.
// smem: Wq_t(64K) Wk_t(64K) P(32K) QS(32K) KG(32K) wgb(2.5K) = 231936 B
// ---------------------------------------------------------------------------
#define SM1_WQ   0
#define SM1_WK   16384
#define SM1_P    32768
#define SM1_QS   40960
#define SM1_KG   49152
#define SM1_WGB  57344
#define SM1_FLOATS 57984

__global__ __launch_bounds__(256, 1) void pass1_kernel(
    const float* __restrict__ pc, const float* __restrict__ x)
{
    extern __shared__ float sm[];
    float* WQs  = sm + SM1_WQ;    // [c][o]
    float* WKs  = sm + SM1_WK;    // [c][o]
    float* Ps   = sm + SM1_P;     // [c][64]
    float* QSs  = sm + SM1_QS;    // [n][o]
    float* KGs  = sm + SM1_KG;    // [n][o]
    float* WGBs = sm + SM1_WGB;   // [o][5]

    const int t = threadIdx.x;
    const int s = blockIdx.x;
    const int b = blockIdx.y;
    const int n_start = s * SPLEN;
    const int n_end   = min(n_start + SPLEN, Nn);

    // stage weights
    for (int i = t; i < Cn * Cn / 4; i += 256) {
        ((float4*)WQs)[i] = ((const float4*)d_Wq)[i];
        ((float4*)WKs)[i] = ((const float4*)d_Wk)[i];
    }
    for (int i = t; i < Cn * 5; i += 256) WGBs[i] = d_wgb[i];

    const int to = (t & 31) * 4;     // projection: 4 output channels
    const int tn = (t >> 5) * 8;     // projection: 8 n positions
    const int tc = (t & 31) * 4;     // attn: 4 c
    const int td = (t >> 5) * 16;    // attn: 16 d

    float sq4[4], sk4[4];
#pragma unroll
    for (int i = 0; i < 4; i++) { sq4[i] = d_sq[to + i]; sk4[i] = d_sk[to + i]; }

    float acc[4][16];
#pragma unroll
    for (int i = 0; i < 4; i++)
#pragma unroll
        for (int j = 0; j < 16; j++) acc[i][j] = 0.f;

    const float* pcb = pc + (size_t)b * Cn * Nn;
    const float* xb  = x  + (size_t)b * 4  * Nn;

    __syncthreads();

    for (int n0 = n_start; n0 < n_end; n0 += TN) {
        const int rem = n_end - n0;
        // ---- load P chunk (128 x 64) ----
        if (rem >= TN) {
#pragma unroll
            for (int i = 0; i < 8; i++) {
                int f = t + 256 * i;          // 2048 float4s
                int c = f >> 4, p = f & 15;
                ((float4*)Ps)[c * 16 + p] =
                    *(const float4*)(pcb + c * Nn + n0 + p * 4);
            }
        } else {
            for (int i = 0; i < 32; i++) {
                int e = t + 256 * i;          // 8192 floats
                int c = e >> 6, j = e & 63;
                Ps[c * 64 + j] = (j < rem) ? pcb[c * Nn + n0 + j] : 0.f;
            }
        }
        __syncthreads();

        // ---- projection: q and k tiles (4o x 8n per thread) ----
        float qa[8][4], ka[8][4];
#pragma unroll
        for (int j = 0; j < 8; j++)
#pragma unroll
            for (int i = 0; i < 4; i++) { qa[j][i] = 0.f; ka[j][i] = 0.f; }

#pragma unroll 4
        for (int c = 0; c < Cn; c++) {
            float4 w  = *(const float4*)&WQs[c * Cn + to];
            float4 u  = *(const float4*)&WKs[c * Cn + to];
            float4 p0 = *(const float4*)&Ps[c * 64 + tn];
            float4 p1 = *(const float4*)&Ps[c * 64 + tn + 4];
            float pj[8] = {p0.x, p0.y, p0.z, p0.w, p1.x, p1.y, p1.z, p1.w};
            float wi[4] = {w.x, w.y, w.z, w.w};
            float ui[4] = {u.x, u.y, u.z, u.w};
#pragma unroll
            for (int j = 0; j < 8; j++)
#pragma unroll
                for (int i = 0; i < 4; i++) {
                    qa[j][i] += wi[i] * pj[j];
                    ka[j][i] += ui[i] * pj[j];
                }
        }

        // ---- epilogue: BN shift + relu, add graph-context, write [n][o] ----
#pragma unroll
        for (int j = 0; j < 8; j++) {
            int gn = n0 + tn + j;
            bool ok = gn < n_end;
            float x0 = 0.f, x1 = 0.f, x2 = 0.f, x3 = 0.f;
            if (ok) {
                x0 = xb[0 * Nn + gn]; x1 = xb[1 * Nn + gn];
                x2 = xb[2 * Nn + gn]; x3 = xb[3 * Nn + gn];
            }
            float qq[4], kk[4];
#pragma unroll
            for (int i = 0; i < 4; i++) {
                float q = fmaxf(qa[j][i] + sq4[i], 0.f);
                float k = fmaxf(ka[j][i] + sk4[i], 0.f);
                const float* w = &WGBs[(to + i) * 5];
                k += w[0] * x0 + w[1] * x1 + w[2] * x2 + w[3] * x3 + w[4];
                if (!ok) { q = 0.f; k = 0.f; }
                qq[i] = q; kk[i] = k;
            }
            *(float4*)&QSs[(tn + j) * Cn + to] = make_float4(qq[0], qq[1], qq[2], qq[3]);
            *(float4*)&KGs[(tn + j) * Cn + to] = make_float4(kk[0], kk[1], kk[2], kk[3]);
        }
        __syncthreads();

        // ---- attn accumulate: acc[c][d] += sum_n QS[n][c]*KG[n][d] ----
#pragma unroll 4
        for (int n = 0; n < TN; n++) {
            float4 q  = *(const float4*)&QSs[n * Cn + tc];
            float4 g0 = *(const float4*)&KGs[n * Cn + td];
            float4 g1 = *(const float4*)&KGs[n * Cn + td + 4];
            float4 g2 = *(const float4*)&KGs[n * Cn + td + 8];
            float4 g3 = *(const float4*)&KGs[n * Cn + td + 12];
            float qv[4]  = {q.x, q.y, q.z, q.w};
            float gv16[16] = {g0.x, g0.y, g0.z, g0.w, g1.x, g1.y, g1.z, g1.w,
                              g2.x, g2.y, g2.z, g2.w, g3.x, g3.y, g3.z, g3.w};
#pragma unroll
            for (int i = 0; i < 4; i++)
#pragma unroll
                for (int j = 0; j < 16; j++)
                    acc[i][j] += qv[i] * gv16[j];
        }
        __syncthreads();
    }

    // ---- store partials ----
    float* dst = d_attn_part + ((size_t)(b * SPL + s)) * Cn * Cn;
#pragma unroll
    for (int i = 0; i < 4; i++)
#pragma unroll
        for (int j = 0; j < 16; j += 4)
            *(float4*)&dst[(tc + i) * Cn + td + j] =
                make_float4(acc[i][j], acc[i][j + 1], acc[i][j + 2], acc[i][j + 3]);
}

// ---------------------------------------------------------------------------
// pass2: reduce 18 partials, softmax over d, store transposed [b][d][c]
// ---------------------------------------------------------------------------
__global__ void pass2_kernel()
{
    const int c = blockIdx.x;
    const int b = blockIdx.y;
    const int d = threadIdx.x;   // 128 threads

    const float* p = d_attn_part + ((size_t)(b * SPL) * Cn + c) * Cn + d;
    float v = 0.f;
#pragma unroll
    for (int s = 0; s < SPL; s++) v += p[(size_t)s * Cn * Cn];

    __shared__ float redm[4], reds[4];
    float m = v;
#pragma unroll
    for (int o = 16; o; o >>= 1) m = fmaxf(m, __shfl_xor_sync(0xffffffffu, m, o));
    if ((d & 31) == 0) redm[d >> 5] = m;
    __syncthreads();
    m = fmaxf(fmaxf(redm[0], redm[1]), fmaxf(redm[2], redm[3]));

    float e = expf(v - m);
    float ss = e;
#pragma unroll
    for (int o = 16; o; o >>= 1) ss += __shfl_xor_sync(0xffffffffu, ss, o);
    if ((d & 31) == 0) reds[d >> 5] = ss;
    __syncthreads();
    ss = reds[0] + reds[1] + reds[2] + reds[3];

    d_attnT[((size_t)b * Cn + d) * Cn + c] = e / ss;
}

// ---------------------------------------------------------------------------
// pass3: v = relu(BN(Wv@pc)) chunks, out = attn@v; coalesced output via smem
// smem: Wv_t(64K) A_t(64K) P(32K) VS(32K) OB(32.5K) = 229888 B
// ---------------------------------------------------------------------------
#define SM3_WV  0
#define SM3_AT  16384
#define SM3_P   32768
#define SM3_VS  40960
#define SM3_OB  49152          // [c][65] staging (stride 65 avoids conflicts)
#define SM3_FLOATS (49152 + 128 * 65)

__global__ __launch_bounds__(256, 1) void pass3_kernel(
    const float* __restrict__ pc, float* __restrict__ out)
{
    extern __shared__ float sm[];
    float* WVs = sm + SM3_WV;    // [c][o]
    float* ATs = sm + SM3_AT;    // [d][c]
    float* Ps  = sm + SM3_P;     // [c][64]
    float* VSs = sm + SM3_VS;    // [n][d]
    float* OBs = sm + SM3_OB;    // [c][65]

    const int t = threadIdx.x;
    const int s = blockIdx.x;
    const int b = blockIdx.y;
    const int n_start = s * SPLEN;
    const int n_end   = min(n_start + SPLEN, Nn);

    const float4* atb = (const float4*)(d_attnT + (size_t)b * Cn * Cn);
    for (int i = t; i < Cn * Cn / 4; i += 256) {
        ((float4*)WVs)[i] = ((const float4*)d_Wv)[i];
        ((float4*)ATs)[i] = atb[i];
    }

    const int to = (t & 31) * 4;     // v projection: 4 channels x 8 n
    const int tn = (t >> 5) * 8;
    const int tc = (t & 31) * 4;     // out: 4 c x 8 n
    float sv4[4];
#pragma unroll
    for (int i = 0; i < 4; i++) sv4[i] = d_sv[to + i];

    const float* pcb = pc + (size_t)b * Cn * Nn;
    float* outb = out + (size_t)b * Cn * Nn;

    __syncthreads();

    for (int n0 = n_start; n0 < n_end; n0 += TN) {
        const int rem = n_end - n0;
        // ---- load P chunk ----
        if (rem >= TN) {
#pragma unroll
            for (int i = 0; i < 8; i++) {
                int f = t + 256 * i;
                int c = f >> 4, p = f & 15;
                ((float4*)Ps)[c * 16 + p] =
                    *(const float4*)(pcb + c * Nn + n0 + p * 4);
            }
        } else {
            for (int i = 0; i < 32; i++) {
                int e = t + 256 * i;
                int c = e >> 6, j = e & 63;
                Ps[c * 64 + j] = (j < rem) ? pcb[c * Nn + n0 + j] : 0.f;
            }
        }
        __syncthreads();

        // ---- v projection ----
        float va[8][4];
#pragma unroll
        for (int j = 0; j < 8; j++)
#pragma unroll
            for (int i = 0; i < 4; i++) va[j][i] = 0.f;

#pragma unroll 4
        for (int c = 0; c < Cn; c++) {
            float4 w  = *(const float4*)&WVs[c * Cn + to];
            float4 p0 = *(const float4*)&Ps[c * 64 + tn];
            float4 p1 = *(const float4*)&Ps[c * 64 + tn + 4];
            float pj[8] = {p0.x, p0.y, p0.z, p0.w, p1.x, p1.y, p1.z, p1.w};
            float wi[4] = {w.x, w.y, w.z, w.w};
#pragma unroll
            for (int j = 0; j < 8; j++)
#pragma unroll
                for (int i = 0; i < 4; i++) va[j][i] += wi[i] * pj[j];
        }
#pragma unroll
        for (int j = 0; j < 8; j++) {
            int gn = n0 + tn + j;
            bool ok = gn < n_end;
            float vv[4];
#pragma unroll
            for (int i = 0; i < 4; i++)
                vv[i] = ok ? fmaxf(va[j][i] + sv4[i], 0.f) : 0.f;
            *(float4*)&VSs[(tn + j) * Cn + to] = make_float4(vv[0], vv[1], vv[2], vv[3]);
        }
        __syncthreads();

        // ---- out = attn @ v (4c x 8n per thread) ----
        float oa[8][4];
#pragma unroll
        for (int j = 0; j < 8; j++)
#pragma unroll
            for (int i = 0; i < 4; i++) oa[j][i] = 0.f;

#pragma unroll 4
        for (int d = 0; d < Cn; d++) {
            float4 a = *(const float4*)&ATs[d * Cn + tc];
            float ai[4] = {a.x, a.y, a.z, a.w};
            float vv[8];
#pragma unroll
            for (int j = 0; j < 8; j++) vv[j] = VSs[(tn + j) * Cn + d];
#pragma unroll
            for (int j = 0; j < 8; j++)
#pragma unroll
                for (int i = 0; i < 4; i++) oa[j][i] += ai[i] * vv[j];
        }
        __syncthreads();   // VSs free; OBs ready for reuse

        // ---- stage output [c][n] then coalesced store ----
#pragma unroll
        for (int j = 0; j < 8; j++)
#pragma unroll
            for (int i = 0; i < 4; i++)
                OBs[(tc + i) * 65 + tn + j] = oa[j][i];
        __syncthreads();

        for (int i = 0; i < 32; i++) {
            int e = t + 256 * i;
            int c = e >> 6, j = e & 63;
            if (j < rem) outb[c * Nn + n0 + j] = OBs[c * 65 + j];
        }
        __syncthreads();
    }
}

// ---------------------------------------------------------------------------
extern "C" void kernel_launch(void* const* d_in, const int* in_sizes, int n_in,
                              void* d_out, int out_size)
{
    const float* pc = (const float*)d_in[0];
    const float* x  = (const float*)d_in[1];

    prep_kernel<<<Cn, Cn>>>(
        (const float*)d_in[2],  (const float*)d_in[3],  (const float*)d_in[4],
        (const float*)d_in[5],  (const float*)d_in[6],
        (const float*)d_in[7],  (const float*)d_in[8],  (const float*)d_in[9],
        (const float*)d_in[10], (const float*)d_in[11],
        (const float*)d_in[12], (const float*)d_in[13], (const float*)d_in[14],
        (const float*)d_in[15], (const float*)d_in[16],
        (const float*)d_in[17], (const float*)d_in[18],
        (const float*)d_in[19], (const float*)d_in[20]);

    cudaFuncSetAttribute(pass1_kernel,
                         cudaFuncAttributeMaxDynamicSharedMemorySize,
                         SM1_FLOATS * 4);
    pass1_kernel<<<dim3(SPL, Bn), 256, SM1_FLOATS * 4>>>(pc, x);

    pass2_kernel<<<dim3(Cn, Bn), Cn>>>();

    cudaFuncSetAttribute(pass3_kernel,
                         cudaFuncAttributeMaxDynamicSharedMemorySize,
                         SM3_FLOATS * 4);
    pass3_kernel<<<dim3(SPL, Bn), 256, SM3_FLOATS * 4>>>(pc, (float*)d_out);
}

// round 2
// speedup vs baseline: 1.0030x; 1.0030x over previous
#include <cuda_runtime.h>
#include <math.h>

#define Bn 8
#define Cn 128
#define Nn 20000
#define TN 64
#define SPL 18
#define SPLEN 1152          // 18*64, SPL*SPLEN = 20736 >= 20000
#define INVT 0.08838834764831845f  // 1/sqrt(128)

// ---- device scratch (static, allocation-free) ----
__device__ __align__(16) float d_Wq[Cn * Cn];   // [c][o], BN scale * 1/temp folded
__device__ __align__(16) float d_Wk[Cn * Cn];   // [c][o], BN scale folded
__device__ __align__(16) float d_Wv[Cn * Cn];   // [c][o], BN scale folded
__device__ float d_sq[Cn], d_sk[Cn], d_sv[Cn];
__device__ float d_wgb[Cn * 5];                 // per o: wg1_0, wg1_1, wg2_0, wg2_1, bg1+bg2
__device__ __align__(16) float d_attn_part[Bn * SPL * Cn * Cn]; // 9.4 MB partials
__device__ __align__(16) float d_attnT[Bn * Cn * Cn];           // softmaxed attn, [b][d][c]

// ---------------------------------------------------------------------------
// prep: fold BN affine (and 1/temp for q) into weights; build graph-bias table
// ---------------------------------------------------------------------------
__global__ void prep_kernel(
    const float* __restrict__ Wq, const float* __restrict__ gq, const float* __restrict__ bq,
    const float* __restrict__ mq, const float* __restrict__ vq,
    const float* __restrict__ Wk, const float* __restrict__ gk, const float* __restrict__ bk,
    const float* __restrict__ mk, const float* __restrict__ vk,
    const float* __restrict__ Wv, const float* __restrict__ gv, const float* __restrict__ bv,
    const float* __restrict__ mv, const float* __restrict__ vv,
    const float* __restrict__ Wg1, const float* __restrict__ bg1,
    const float* __restrict__ Wg2, const float* __restrict__ bg2)
{
    int o = blockIdx.x;
    int c = threadIdx.x;
    float scq = gq[o] / sqrtf(vq[o] + 1e-5f);
    float sck = gk[o] / sqrtf(vk[o] + 1e-5f);
    float scv = gv[o] / sqrtf(vv[o] + 1e-5f);
    d_Wq[c * Cn + o] = Wq[o * Cn + c] * scq * INVT;
    d_Wk[c * Cn + o] = Wk[o * Cn + c] * sck;
    d_Wv[c * Cn + o] = Wv[o * Cn + c] * scv;
    if (c == 0) {
        d_sq[o] = (bq[o] - mq[o] * scq) * INVT;
        d_sk[o] = bk[o] - mk[o] * sck;
        d_sv[o] = bv[o] - mv[o] * scv;
        d_wgb[o * 5 + 0] = Wg1[o * 2 + 0];
        d_wgb[o * 5 + 1] = Wg1[o * 2 + 1];
        d_wgb[o * 5 + 2] = Wg2[o * 2 + 0];
        d_wgb[o * 5 + 3] = Wg2[o * 2 + 1];
        d_wgb[o * 5 + 4] = bg1[o] + bg2[o];
    }
}

// ---------------------------------------------------------------------------
// pass1: per (split, b) block — compute q, k+gc chunks on the fly and
// accumulate attn partials (128x128) in registers. No q/k ever hit HBM.
// smem: Wq_t(64K) Wk_t(64K) P(32K) QS(32K) KG(32K) wgb(2.5K) = 231936 B
// ---------------------------------------------------------------------------
#define SM1_WQ   0
#define SM1_WK   16384
#define SM1_P    32768
#define SM1_QS   40960
#define SM1_KG   49152
#define SM1_WGB  57344
#define SM1_FLOATS 57984

__global__ __launch_bounds__(256, 1) void pass1_kernel(
    const float* __restrict__ pc, const float* __restrict__ x)
{
    extern __shared__ float sm[];
    float* WQs  = sm + SM1_WQ;    // [c][o]
    float* WKs  = sm + SM1_WK;    // [c][o]
    float* Ps   = sm + SM1_P;     // [c][64]
    float* QSs  = sm + SM1_QS;    // [n][o]
    float* KGs  = sm + SM1_KG;    // [n][o]
    float* WGBs = sm + SM1_WGB;   // [o][5]

    const int t = threadIdx.x;
    const int s = blockIdx.x;
    const int b = blockIdx.y;
    const int n_start = s * SPLEN;
    const int n_end   = min(n_start + SPLEN, Nn);

    // stage weights
    for (int i = t; i < Cn * Cn / 4; i += 256) {
        ((float4*)WQs)[i] = ((const float4*)d_Wq)[i];
        ((float4*)WKs)[i] = ((const float4*)d_Wk)[i];
    }
    for (int i = t; i < Cn * 5; i += 256) WGBs[i] = d_wgb[i];

    const int to = (t & 31) * 4;     // projection: 4 output channels
    const int tn = (t >> 5) * 8;     // projection: 8 n positions
    const int tc = (t & 31) * 4;     // attn: 4 c
    const int td = (t >> 5) * 16;    // attn: 16 d

    float sq4[4], sk4[4];
#pragma unroll
    for (int i = 0; i < 4; i++) { sq4[i] = d_sq[to + i]; sk4[i] = d_sk[to + i]; }

    float acc[4][16];
#pragma unroll
    for (int i = 0; i < 4; i++)
#pragma unroll
        for (int j = 0; j < 16; j++) acc[i][j] = 0.f;

    const float* pcb = pc + (size_t)b * Cn * Nn;
    const float* xb  = x  + (size_t)b * 4  * Nn;

    __syncthreads();

    for (int n0 = n_start; n0 < n_end; n0 += TN) {
        const int rem = n_end - n0;
        // ---- load P chunk (128 x 64) ----
        if (rem >= TN) {
#pragma unroll
            for (int i = 0; i < 8; i++) {
                int f = t + 256 * i;          // 2048 float4s
                int c = f >> 4, p = f & 15;
                ((float4*)Ps)[c * 16 + p] =
                    *(const float4*)(pcb + c * Nn + n0 + p * 4);
            }
        } else {
            for (int i = 0; i < 32; i++) {
                int e = t + 256 * i;          // 8192 floats
                int c = e >> 6, j = e & 63;
                Ps[c * 64 + j] = (j < rem) ? pcb[c * Nn + n0 + j] : 0.f;
            }
        }
        __syncthreads();

        // ---- projection: q and k tiles (4o x 8n per thread) ----
        float qa[8][4], ka[8][4];
#pragma unroll
        for (int j = 0; j < 8; j++)
#pragma unroll
            for (int i = 0; i < 4; i++) { qa[j][i] = 0.f; ka[j][i] = 0.f; }

#pragma unroll 4
        for (int c = 0; c < Cn; c++) {
            float4 w  = *(const float4*)&WQs[c * Cn + to];
            float4 u  = *(const float4*)&WKs[c * Cn + to];
            float4 p0 = *(const float4*)&Ps[c * 64 + tn];
            float4 p1 = *(const float4*)&Ps[c * 64 + tn + 4];
            float pj[8] = {p0.x, p0.y, p0.z, p0.w, p1.x, p1.y, p1.z, p1.w};
            float wi[4] = {w.x, w.y, w.z, w.w};
            float ui[4] = {u.x, u.y, u.z, u.w};
#pragma unroll
            for (int j = 0; j < 8; j++)
#pragma unroll
                for (int i = 0; i < 4; i++) {
                    qa[j][i] += wi[i] * pj[j];
                    ka[j][i] += ui[i] * pj[j];
                }
        }

        // ---- epilogue: BN shift + relu, add graph-context, write [n][o] ----
#pragma unroll
        for (int j = 0; j < 8; j++) {
            int gn = n0 + tn + j;
            bool ok = gn < n_end;
            float x0 = 0.f, x1 = 0.f, x2 = 0.f, x3 = 0.f;
            if (ok) {
                x0 = xb[0 * Nn + gn]; x1 = xb[1 * Nn + gn];
                x2 = xb[2 * Nn + gn]; x3 = xb[3 * Nn + gn];
            }
            float qq[4], kk[4];
#pragma unroll
            for (int i = 0; i < 4; i++) {
                float q = fmaxf(qa[j][i] + sq4[i], 0.f);
                float k = fmaxf(ka[j][i] + sk4[i], 0.f);
                const float* w = &WGBs[(to + i) * 5];
                k += w[0] * x0 + w[1] * x1 + w[2] * x2 + w[3] * x3 + w[4];
                if (!ok) { q = 0.f; k = 0.f; }
                qq[i] = q; kk[i] = k;
            }
            *(float4*)&QSs[(tn + j) * Cn + to] = make_float4(qq[0], qq[1], qq[2], qq[3]);
            *(float4*)&KGs[(tn + j) * Cn + to] = make_float4(kk[0], kk[1], kk[2], kk[3]);
        }
        __syncthreads();

        // ---- attn accumulate: acc[c][d] += sum_n QS[n][c]*KG[n][d] ----
#pragma unroll 4
        for (int n = 0; n < TN; n++) {
            float4 q  = *(const float4*)&QSs[n * Cn + tc];
            float4 g0 = *(const float4*)&KGs[n * Cn + td];
            float4 g1 = *(const float4*)&KGs[n * Cn + td + 4];
            float4 g2 = *(const float4*)&KGs[n * Cn + td + 8];
            float4 g3 = *(const float4*)&KGs[n * Cn + td + 12];
            float qv[4]  = {q.x, q.y, q.z, q.w};
            float gv16[16] = {g0.x, g0.y, g0.z, g0.w, g1.x, g1.y, g1.z, g1.w,
                              g2.x, g2.y, g2.z, g2.w, g3.x, g3.y, g3.z, g3.w};
#pragma unroll
            for (int i = 0; i < 4; i++)
#pragma unroll
                for (int j = 0; j < 16; j++)
                    acc[i][j] += qv[i] * gv16[j];
        }
        __syncthreads();
    }

    // ---- store partials ----
    float* dst = d_attn_part + ((size_t)(b * SPL + s)) * Cn * Cn;
#pragma unroll
    for (int i = 0; i < 4; i++)
#pragma unroll
        for (int j = 0; j < 16; j += 4)
            *(float4*)&dst[(tc + i) * Cn + td + j] =
                make_float4(acc[i][j], acc[i][j + 1], acc[i][j + 2], acc[i][j + 3]);
}

// ---------------------------------------------------------------------------
// pass2: reduce 18 partials, softmax over d, store transposed [b][d][c]
// ---------------------------------------------------------------------------
__global__ void pass2_kernel()
{
    const int c = blockIdx.x;
    const int b = blockIdx.y;
    const int d = threadIdx.x;   // 128 threads

    const float* p = d_attn_part + ((size_t)(b * SPL) * Cn + c) * Cn + d;
    float v = 0.f;
#pragma unroll
    for (int s = 0; s < SPL; s++) v += p[(size_t)s * Cn * Cn];

    __shared__ float redm[4], reds[4];
    float m = v;
#pragma unroll
    for (int o = 16; o; o >>= 1) m = fmaxf(m, __shfl_xor_sync(0xffffffffu, m, o));
    if ((d & 31) == 0) redm[d >> 5] = m;
    __syncthreads();
    m = fmaxf(fmaxf(redm[0], redm[1]), fmaxf(redm[2], redm[3]));

    float e = expf(v - m);
    float ss = e;
#pragma unroll
    for (int o = 16; o; o >>= 1) ss += __shfl_xor_sync(0xffffffffu, ss, o);
    if ((d & 31) == 0) reds[d >> 5] = ss;
    __syncthreads();
    ss = reds[0] + reds[1] + reds[2] + reds[3];

    d_attnT[((size_t)b * Cn + d) * Cn + c] = e / ss;
}

// ---------------------------------------------------------------------------
// pass3: v = relu(BN(Wv@pc)) chunks, out = attn@v; coalesced output via smem
// smem: Wv_t(64K) A_t(64K) P(32K) VS(32K) OB(32.5K) = 229888 B
// ---------------------------------------------------------------------------
#define SM3_WV  0
#define SM3_AT  16384
#define SM3_P   32768
#define SM3_VS  40960
#define SM3_OB  49152          // [c][65] staging (stride 65 avoids conflicts)
#define SM3_FLOATS (49152 + 128 * 65)

__global__ __launch_bounds__(256, 1) void pass3_kernel(
    const float* __restrict__ pc, float* __restrict__ out)
{
    extern __shared__ float sm[];
    float* WVs = sm + SM3_WV;    // [c][o]
    float* ATs = sm + SM3_AT;    // [d][c]
    float* Ps  = sm + SM3_P;     // [c][64]
    float* VSs = sm + SM3_VS;    // [n][d]
    float* OBs = sm + SM3_OB;    // [c][65]

    const int t = threadIdx.x;
    const int s = blockIdx.x;
    const int b = blockIdx.y;
    const int n_start = s * SPLEN;
    const int n_end   = min(n_start + SPLEN, Nn);

    const float4* atb = (const float4*)(d_attnT + (size_t)b * Cn * Cn);
    for (int i = t; i < Cn * Cn / 4; i += 256) {
        ((float4*)WVs)[i] = ((const float4*)d_Wv)[i];
        ((float4*)ATs)[i] = atb[i];
    }

    const int to = (t & 31) * 4;     // v projection: 4 channels x 8 n
    const int tn = (t >> 5) * 8;
    const int tc = (t & 31) * 4;     // out: 4 c x 8 n
    float sv4[4];
#pragma unroll
    for (int i = 0; i < 4; i++) sv4[i] = d_sv[to + i];

    const float* pcb = pc + (size_t)b * Cn * Nn;
    float* outb = out + (size_t)b * Cn * Nn;

    __syncthreads();

    for (int n0 = n_start; n0 < n_end; n0 += TN) {
        const int rem = n_end - n0;
        // ---- load P chunk ----
        if (rem >= TN) {
#pragma unroll
            for (int i = 0; i < 8; i++) {
                int f = t + 256 * i;
                int c = f >> 4, p = f & 15;
                ((float4*)Ps)[c * 16 + p] =
                    *(const float4*)(pcb + c * Nn + n0 + p * 4);
            }
        } else {
            for (int i = 0; i < 32; i++) {
                int e = t + 256 * i;
                int c = e >> 6, j = e & 63;
                Ps[c * 64 + j] = (j < rem) ? pcb[c * Nn + n0 + j] : 0.f;
            }
        }
        __syncthreads();

        // ---- v projection ----
        float va[8][4];
#pragma unroll
        for (int j = 0; j < 8; j++)
#pragma unroll
            for (int i = 0; i < 4; i++) va[j][i] = 0.f;

#pragma unroll 4
        for (int c = 0; c < Cn; c++) {
            float4 w  = *(const float4*)&WVs[c * Cn + to];
            float4 p0 = *(const float4*)&Ps[c * 64 + tn];
            float4 p1 = *(const float4*)&Ps[c * 64 + tn + 4];
            float pj[8] = {p0.x, p0.y, p0.z, p0.w, p1.x, p1.y, p1.z, p1.w};
            float wi[4] = {w.x, w.y, w.z, w.w};
#pragma unroll
            for (int j = 0; j < 8; j++)
#pragma unroll
                for (int i = 0; i < 4; i++) va[j][i] += wi[i] * pj[j];
        }
#pragma unroll
        for (int j = 0; j < 8; j++) {
            int gn = n0 + tn + j;
            bool ok = gn < n_end;
            float vv[4];
#pragma unroll
            for (int i = 0; i < 4; i++)
                vv[i] = ok ? fmaxf(va[j][i] + sv4[i], 0.f) : 0.f;
            *(float4*)&VSs[(tn + j) * Cn + to] = make_float4(vv[0], vv[1], vv[2], vv[3]);
        }
        __syncthreads();

        // ---- out = attn @ v (4c x 8n per thread) ----
        float oa[8][4];
#pragma unroll
        for (int j = 0; j < 8; j++)
#pragma unroll
            for (int i = 0; i < 4; i++) oa[j][i] = 0.f;

#pragma unroll 4
        for (int d = 0; d < Cn; d++) {
            float4 a = *(const float4*)&ATs[d * Cn + tc];
            float ai[4] = {a.x, a.y, a.z, a.w};
            float vv[8];
#pragma unroll
            for (int j = 0; j < 8; j++) vv[j] = VSs[(tn + j) * Cn + d];
#pragma unroll
            for (int j = 0; j < 8; j++)
#pragma unroll
                for (int i = 0; i < 4; i++) oa[j][i] += ai[i] * vv[j];
        }
        __syncthreads();   // VSs free; OBs ready for reuse

        // ---- stage output [c][n] then coalesced store ----
#pragma unroll
        for (int j = 0; j < 8; j++)
#pragma unroll
            for (int i = 0; i < 4; i++)
                OBs[(tc + i) * 65 + tn + j] = oa[j][i];
        __syncthreads();

        for (int i = 0; i < 32; i++) {
            int e = t + 256 * i;
            int c = e >> 6, j = e & 63;
            if (j < rem) outb[c * Nn + n0 + j] = OBs[c * 65 + j];
        }
        __syncthreads();
    }
}

// ---------------------------------------------------------------------------
extern "C" void kernel_launch(void* const* d_in, const int* in_sizes, int n_in,
                              void* d_out, int out_size)
{
    const float* pc = (const float*)d_in[0];
    const float* x  = (const float*)d_in[1];

    prep_kernel<<<Cn, Cn>>>(
        (const float*)d_in[2],  (const float*)d_in[3],  (const float*)d_in[4],
        (const float*)d_in[5],  (const float*)d_in[6],
        (const float*)d_in[7],  (const float*)d_in[8],  (const float*)d_in[9],
        (const float*)d_in[10], (const float*)d_in[11],
        (const float*)d_in[12], (const float*)d_in[13], (const float*)d_in[14],
        (const float*)d_in[15], (const float*)d_in[16],
        (const float*)d_in[17], (const float*)d_in[18],
        (const float*)d_in[19], (const float*)d_in[20]);

    cudaFuncSetAttribute(pass1_kernel,
                         cudaFuncAttributeMaxDynamicSharedMemorySize,
                         SM1_FLOATS * 4);
    pass1_kernel<<<dim3(SPL, Bn), 256, SM1_FLOATS * 4>>>(pc, x);

    pass2_kernel<<<dim3(Cn, Bn), Cn>>>();

    cudaFuncSetAttribute(pass3_kernel,
                         cudaFuncAttributeMaxDynamicSharedMemorySize,
                         SM3_FLOATS * 4);
    pass3_kernel<<<dim3(SPL, Bn), 256, SM3_FLOATS * 4>>>(pc, (float*)d_out);
}